// round 1
// baseline (speedup 1.0000x reference)
#include <cuda_runtime.h>
#include <cuda_bf16.h>

// ---------------------------------------------------------------------------
// Problem constants
// ---------------------------------------------------------------------------
#define LAYERS 4
#define NB 2
#define NC 3
#define D1 48
#define D2 48
#define D3 48
#define D4 24
#define NSP  (D1*D2*D3*D4)        // 2,654,208 spatial points per channel
#define CN   (NC*NSP)             // 7,962,624 elems per batch image

// ---------------------------------------------------------------------------
// Scratch: batch-interleaved tensors, float2 = {b0, b1}
// ---------------------------------------------------------------------------
__device__ float2 s_fi[CN];   // packed f
__device__ float2 s_bi[CN];   // packed boundary
__device__ float2 s_g [CN];   // Wg output
__device__ float2 s_t [CN];   // W1 output
__device__ float2 s_oA[CN];   // ping
__device__ float2 s_oB[CN];   // pong

// ---------------------------------------------------------------------------
// packed fp32x2 FMA (FFMA2) — full-rate fp32 path on sm_103a
// ---------------------------------------------------------------------------
__device__ __forceinline__ float2 ffma2(float2 a, float2 b, float2 c) {
    unsigned long long ua, ub, uc, ud;
    ua = *reinterpret_cast<const unsigned long long*>(&a);
    ub = *reinterpret_cast<const unsigned long long*>(&b);
    uc = *reinterpret_cast<const unsigned long long*>(&c);
    asm("fma.rn.f32x2 %0, %1, %2, %3;" : "=l"(ud) : "l"(ua), "l"(ub), "l"(uc));
    return *reinterpret_cast<float2*>(&ud);
}

// ---------------------------------------------------------------------------
// Pack f / boundary into interleaved layout
// ---------------------------------------------------------------------------
__global__ void pack_kernel(const float* __restrict__ f,
                            const float* __restrict__ bnd,
                            float2* __restrict__ fi,
                            float2* __restrict__ bi) {
    int i = blockIdx.x * blockDim.x + threadIdx.x;
    if (i < CN) {
        fi[i] = make_float2(f[i],   f[i + CN]);
        bi[i] = make_float2(bnd[i], bnd[i + CN]);
    }
}

// ---------------------------------------------------------------------------
// Wg conv: 6 in ch (inA = prev out, inB = boundary), 3 out ch, 3x3x3x3, pad 1
// Block: one x1 plane, 4(x2) x 8(x3) tile, full x4=24 (4 threads x 6 outputs)
// ---------------------------------------------------------------------------
__global__ __launch_bounds__(128) void wg_kernel(
    const float2* __restrict__ inA, const float2* __restrict__ inB,
    const float*  __restrict__ W,   const float*  __restrict__ bias,
    float2* __restrict__ out)
{
    __shared__ float2 sW[6][3][3][3][9];     // [ci][k1][k2][k3][co*3+k4], dup'd
    __shared__ float2 sIn[3][6][10][26];     // [p1][p2][p3][p4] per-ci stage

    const int tid = threadIdx.x;
    const int q   = tid & 3;          // x4 group: outputs q*6 .. q*6+5
    const int x3l = (tid >> 2) & 7;
    const int x2l = tid >> 5;
    const int x1  = blockIdx.x;
    const int x2b = blockIdx.y * 4;
    const int x3b = blockIdx.z * 8;

    // load + duplicate weights
    for (int s = tid; s < 1458; s += 128) {
        int k4 = s % 3;      int r = s / 3;
        int co = r % 3;      r /= 3;
        int k3 = r % 3;      r /= 3;
        int k2 = r % 3;      r /= 3;
        int k1 = r % 3;      int ci = r / 3;
        float w = W[(co*6 + ci)*81 + ((k1*3 + k2)*3 + k3)*3 + k4];
        ((float2*)sW)[s] = make_float2(w, w);
    }

    float2 acc[3][6];
    #pragma unroll
    for (int co = 0; co < 3; ++co) {
        float b = bias[co];
        #pragma unroll
        for (int j = 0; j < 6; ++j) acc[co][j] = make_float2(b, b);
    }

    for (int ci = 0; ci < 6; ++ci) {
        const float2* __restrict__ src =
            (ci < 3) ? (inA + ci * NSP) : (inB + (ci - 3) * NSP);
        __syncthreads();
        for (int s = tid; s < 3*6*10*26; s += 128) {
            int p4 = s % 26;  int r = s / 26;
            int p3 = r % 10;  r /= 10;
            int p2 = r % 6;   int p1 = r / 6;
            int g1 = x1  - 1 + p1;
            int g2 = x2b - 1 + p2;
            int g3 = x3b - 1 + p3;
            int g4 = p4 - 1;
            float2 v = make_float2(0.f, 0.f);
            if ((unsigned)g1 < (unsigned)D1 && (unsigned)g2 < (unsigned)D2 &&
                (unsigned)g3 < (unsigned)D3 && (unsigned)g4 < (unsigned)D4)
                v = src[((g1*D2 + g2)*D3 + g3)*D4 + g4];
            ((float2*)sIn)[s] = v;
        }
        __syncthreads();

        #pragma unroll 1
        for (int k1 = 0; k1 < 3; ++k1) {
            #pragma unroll
            for (int k2 = 0; k2 < 3; ++k2) {
                #pragma unroll
                for (int k3 = 0; k3 < 3; ++k3) {
                    const float2* ip = &sIn[k1][x2l + k2][x3l + k3][q * 6];
                    float2 iv[8];
                    #pragma unroll
                    for (int j = 0; j < 8; ++j) iv[j] = ip[j];
                    const float2* wp = sW[ci][k1][k2][k3];
                    #pragma unroll
                    for (int co = 0; co < 3; ++co) {
                        #pragma unroll
                        for (int k4 = 0; k4 < 3; ++k4) {
                            float2 w = wp[co*3 + k4];
                            #pragma unroll
                            for (int j = 0; j < 6; ++j)
                                acc[co][j] = ffma2(iv[j + k4], w, acc[co][j]);
                        }
                    }
                }
            }
        }
    }

    const int x2 = x2b + x2l, x3 = x3b + x3l;
    const int base = ((x1*D2 + x2)*D3 + x3)*D4 + q*6;
    #pragma unroll
    for (int co = 0; co < 3; ++co)
        #pragma unroll
        for (int j = 0; j < 6; ++j)
            out[co*NSP + base + j] = acc[co][j];
}

// ---------------------------------------------------------------------------
// W1 conv: 3->3 ch, (3,3,3,1) taps, pad (1,1,1,0)
// ---------------------------------------------------------------------------
__global__ __launch_bounds__(128) void w1_kernel(
    const float2* __restrict__ g,
    const float*  __restrict__ W,  const float* __restrict__ bias,
    float2* __restrict__ out)
{
    __shared__ float2 sW[3][3][3][3][3];     // [ci][k1][k2][k3][co], dup'd
    __shared__ float2 sIn[3][6][10][24];     // per-ci stage, no x4 halo

    const int tid = threadIdx.x;
    const int q   = tid & 3;
    const int x3l = (tid >> 2) & 7;
    const int x2l = tid >> 5;
    const int x1  = blockIdx.x;
    const int x2b = blockIdx.y * 4;
    const int x3b = blockIdx.z * 8;

    for (int s = tid; s < 243; s += 128) {
        int co = s % 3;   int r = s / 3;
        int k3 = r % 3;   r /= 3;
        int k2 = r % 3;   r /= 3;
        int k1 = r % 3;   int ci = r / 3;
        float w = W[(co*3 + ci)*27 + k1*9 + k2*3 + k3];
        ((float2*)sW)[s] = make_float2(w, w);
    }

    float2 acc[3][6];
    #pragma unroll
    for (int co = 0; co < 3; ++co) {
        float b = bias[co];
        #pragma unroll
        for (int j = 0; j < 6; ++j) acc[co][j] = make_float2(b, b);
    }

    for (int ci = 0; ci < 3; ++ci) {
        const float2* __restrict__ src = g + ci * NSP;
        __syncthreads();
        for (int s = tid; s < 3*6*10*24; s += 128) {
            int p4 = s % 24;  int r = s / 24;
            int p3 = r % 10;  r /= 10;
            int p2 = r % 6;   int p1 = r / 6;
            int g1 = x1  - 1 + p1;
            int g2 = x2b - 1 + p2;
            int g3 = x3b - 1 + p3;
            float2 v = make_float2(0.f, 0.f);
            if ((unsigned)g1 < (unsigned)D1 && (unsigned)g2 < (unsigned)D2 &&
                (unsigned)g3 < (unsigned)D3)
                v = src[((g1*D2 + g2)*D3 + g3)*D4 + p4];
            ((float2*)sIn)[s] = v;
        }
        __syncthreads();

        #pragma unroll 1
        for (int k1 = 0; k1 < 3; ++k1) {
            #pragma unroll
            for (int k2 = 0; k2 < 3; ++k2) {
                #pragma unroll
                for (int k3 = 0; k3 < 3; ++k3) {
                    const float2* ip = &sIn[k1][x2l + k2][x3l + k3][q * 6];
                    float2 iv[6];
                    #pragma unroll
                    for (int j = 0; j < 6; ++j) iv[j] = ip[j];
                    #pragma unroll
                    for (int co = 0; co < 3; ++co) {
                        float2 w = sW[ci][k1][k2][k3][co];
                        #pragma unroll
                        for (int j = 0; j < 6; ++j)
                            acc[co][j] = ffma2(iv[j], w, acc[co][j]);
                    }
                }
            }
        }
    }

    const int x2 = x2b + x2l, x3 = x3b + x3l;
    const int base = ((x1*D2 + x2)*D3 + x3)*D4 + q*6;
    #pragma unroll
    for (int co = 0; co < 3; ++co)
        #pragma unroll
        for (int j = 0; j < 6; ++j)
            out[co*NSP + base + j] = acc[co][j];
}

// ---------------------------------------------------------------------------
// Fused epilogue: out_new = conv(t, W2, pad(0,0,0,1)) + b2 + conv(out, Wd) + bd
// Memory-bound. Final layer de-interleaves into standard (B,C,...) d_out.
// ---------------------------------------------------------------------------
__global__ void w2wd_kernel(
    const float2* __restrict__ t,  const float2* __restrict__ op,
    const float*  __restrict__ W2, const float* __restrict__ b2,
    const float*  __restrict__ Wd, const float* __restrict__ bd,
    float2* __restrict__ onew, float* __restrict__ ofinal, int final_layer)
{
    int i = blockIdx.x * blockDim.x + threadIdx.x;
    if (i >= NSP) return;
    int x4 = i % D4;

    float w2r[3][3][3], wdr[3][3];
    #pragma unroll
    for (int co = 0; co < 3; ++co) {
        #pragma unroll
        for (int ci = 0; ci < 3; ++ci) {
            #pragma unroll
            for (int k = 0; k < 3; ++k)
                w2r[co][ci][k] = W2[(co*3 + ci)*3 + k];
            wdr[co][ci] = Wd[co*3 + ci];
        }
    }

    float2 acc[3];
    #pragma unroll
    for (int co = 0; co < 3; ++co) {
        float b = b2[co] + bd[co];
        acc[co] = make_float2(b, b);
    }

    const float2 z = make_float2(0.f, 0.f);
    #pragma unroll
    for (int ci = 0; ci < 3; ++ci) {
        float2 tm = (x4 > 0)      ? t[ci*NSP + i - 1] : z;
        float2 t0 =                 t[ci*NSP + i];
        float2 tp = (x4 < D4 - 1) ? t[ci*NSP + i + 1] : z;
        float2 ov =                 op[ci*NSP + i];
        #pragma unroll
        for (int co = 0; co < 3; ++co) {
            float2 a = acc[co];
            a.x = fmaf(w2r[co][ci][0], tm.x, a.x);
            a.y = fmaf(w2r[co][ci][0], tm.y, a.y);
            a.x = fmaf(w2r[co][ci][1], t0.x, a.x);
            a.y = fmaf(w2r[co][ci][1], t0.y, a.y);
            a.x = fmaf(w2r[co][ci][2], tp.x, a.x);
            a.y = fmaf(w2r[co][ci][2], tp.y, a.y);
            a.x = fmaf(wdr[co][ci],    ov.x, a.x);
            a.y = fmaf(wdr[co][ci],    ov.y, a.y);
            acc[co] = a;
        }
    }

    if (final_layer) {
        #pragma unroll
        for (int co = 0; co < 3; ++co) {
            ofinal[co*NSP + i]      = acc[co].x;
            ofinal[CN + co*NSP + i] = acc[co].y;
        }
    } else {
        #pragma unroll
        for (int co = 0; co < 3; ++co)
            onew[co*NSP + i] = acc[co];
    }
}

// ---------------------------------------------------------------------------
// Driver
// ---------------------------------------------------------------------------
extern "C" void kernel_launch(void* const* d_in, const int* in_sizes, int n_in,
                              void* d_out, int out_size)
{
    const float* f   = (const float*)d_in[0];
    const float* bnd = (const float*)d_in[1];
    const float* Wg  = (const float*)d_in[2];
    const float* bg  = (const float*)d_in[3];
    const float* W1  = (const float*)d_in[4];
    const float* b1  = (const float*)d_in[5];
    const float* W2  = (const float*)d_in[6];
    const float* b2  = (const float*)d_in[7];
    const float* Wd  = (const float*)d_in[8];
    const float* bd  = (const float*)d_in[9];

    float2 *fi, *bi, *gg, *tt, *oA, *oB;
    cudaGetSymbolAddress((void**)&fi, s_fi);
    cudaGetSymbolAddress((void**)&bi, s_bi);
    cudaGetSymbolAddress((void**)&gg, s_g);
    cudaGetSymbolAddress((void**)&tt, s_t);
    cudaGetSymbolAddress((void**)&oA, s_oA);
    cudaGetSymbolAddress((void**)&oB, s_oB);

    pack_kernel<<<(CN + 255) / 256, 256>>>(f, bnd, fi, bi);

    dim3 cgrid(D1, D2 / 4, D3 / 8);
    const float2* cur = fi;
    float2* outs[LAYERS] = {oA, oB, oA, nullptr};

    for (int i = 0; i < LAYERS; ++i) {
        wg_kernel<<<cgrid, 128>>>(cur, bi, Wg + i*1458, bg + i*3, gg);
        w1_kernel<<<cgrid, 128>>>(gg, W1 + i*243, b1 + i*3, tt);
        w2wd_kernel<<<(NSP + 255) / 256, 256>>>(
            tt, cur, W2 + i*27, b2 + i*3, Wd + i*9, bd + i*3,
            outs[i], (float*)d_out, (i == LAYERS - 1) ? 1 : 0);
        cur = outs[i];
    }
}

// round 2
// speedup vs baseline: 1.0863x; 1.0863x over previous
#include <cuda_runtime.h>
#include <cuda_bf16.h>

// ---------------------------------------------------------------------------
// Problem constants
// ---------------------------------------------------------------------------
#define LAYERS 4
#define NC 3
#define D1 48
#define D2 48
#define D3 48
#define D4 24
#define NSP  (D1*D2*D3*D4)        // 2,654,208 spatial points per channel
#define CN   (NC*NSP)             // 7,962,624 elems per batch image

// ---------------------------------------------------------------------------
// Scratch: batch-interleaved tensors, float2 = {b0, b1}
// ---------------------------------------------------------------------------
__device__ float2 s_fi[CN];
__device__ float2 s_bi[CN];
__device__ float2 s_g [CN];
__device__ float2 s_t [CN];
__device__ float2 s_oA[CN];
__device__ float2 s_oB[CN];

// packed fp32x2 FMA (FFMA2) — full-rate fp32 path on sm_103a
__device__ __forceinline__ float2 ffma2(float2 a, float2 b, float2 c) {
    unsigned long long ua, ub, uc, ud;
    ua = *reinterpret_cast<const unsigned long long*>(&a);
    ub = *reinterpret_cast<const unsigned long long*>(&b);
    uc = *reinterpret_cast<const unsigned long long*>(&c);
    asm("fma.rn.f32x2 %0, %1, %2, %3;" : "=l"(ud) : "l"(ua), "l"(ub), "l"(uc));
    return *reinterpret_cast<float2*>(&ud);
}

union IV16 { float4 a[8]; float2 f2[16]; };
union IV12 { float4 a[6]; float2 f2[12]; };

// ---------------------------------------------------------------------------
// Pack f / boundary into interleaved layout (float4 path)
// ---------------------------------------------------------------------------
__global__ void pack_kernel(const float4* __restrict__ f,
                            const float4* __restrict__ bnd,
                            float4* __restrict__ fi,
                            float4* __restrict__ bi) {
    int i = blockIdx.x * blockDim.x + threadIdx.x;   // i over CN/4
    if (i >= CN / 4) return;
    float4 a = f[i],   b = f[i + CN / 4];
    fi[2*i]     = make_float4(a.x, b.x, a.y, b.y);
    fi[2*i + 1] = make_float4(a.z, b.z, a.w, b.w);
    a = bnd[i]; b = bnd[i + CN / 4];
    bi[2*i]     = make_float4(a.x, b.x, a.y, b.y);
    bi[2*i + 1] = make_float4(a.z, b.z, a.w, b.w);
}

// ---------------------------------------------------------------------------
// Wg conv: 6 in ch, 3 out ch, 3x3x3x3 taps, pad (1,1,1,1)
// Tile: x1=2, x2=4, x3=8, x4=24. 128 threads, 12 x4-outputs per thread.
// smem: weights 6*27*10 float2 (12960B) + per-ci input stage [4][6][10][30]
// (57600B). Row stride 30 f2 = 240B = 15*16B (odd*16 -> conflict-free LDS.128).
// ---------------------------------------------------------------------------
#define WG_SMEM_F2 (6*27*10 + 4*6*10*30)   // 1620 + 7200 = 8820 f2 = 70560 B

__global__ __launch_bounds__(128, 3) void wg_kernel(
    const float2* __restrict__ inA, const float2* __restrict__ inB,
    const float*  __restrict__ W,   const float*  __restrict__ bias,
    float2* __restrict__ out)
{
    extern __shared__ float2 dsm[];
    float2* sW  = dsm;                 // [ci*27+k][10]: co*3+k4 in 0..8, pad 9
    float2* sIn = dsm + 6*27*10;       // [p1][p2][p3][30]

    const int tid = threadIdx.x;
    const int x3l = tid & 7;
    const int q   = (tid >> 3) & 1;    // x4 half: outputs q*12 .. q*12+11
    const int x2l = (tid >> 4) & 3;
    const int x1l = tid >> 6;          // 0..1
    const int x1g = blockIdx.x * 2;
    const int x2g = blockIdx.y * 4;
    const int x3g = blockIdx.z * 8;

    // weights -> smem, duplicated to f32x2
    for (int s = tid; s < 6*27; s += 128) {
        int ci = s / 27, k = s % 27;
        #pragma unroll
        for (int e = 0; e < 9; ++e) {
            int co = e / 3, k4 = e % 3;
            float w = W[(co*6 + ci)*81 + k*3 + k4];
            sW[s*10 + e] = make_float2(w, w);
        }
    }

    float2 acc[3][12];
    #pragma unroll
    for (int co = 0; co < 3; ++co) {
        float b = __ldg(bias + co);
        #pragma unroll
        for (int j = 0; j < 12; ++j) acc[co][j] = make_float2(b, b);
    }

    const int lane = tid & 15;   // staging: float4 column 0..14 (15 idle)
    const int slot = tid >> 4;   // staging: row slot 0..7

    for (int ci = 0; ci < 6; ++ci) {
        const float2* __restrict__ src =
            (ci < 3) ? (inA + ci * NSP) : (inB + (ci - 3) * NSP);
        __syncthreads();
        // stage [4][6][10] rows of 15 float4 (p4 = g4+2, interior g4 0..23)
        for (int r = slot; r < 240; r += 8) {
            int p3 = r % 10; int t = r / 10; int p2 = t % 6; int p1 = t / 6;
            int g1 = x1g - 1 + p1, g2 = x2g - 1 + p2, g3 = x3g - 1 + p3;
            float4 v = make_float4(0.f, 0.f, 0.f, 0.f);
            if (lane >= 1 && lane <= 12 &&
                (unsigned)g1 < (unsigned)D1 && (unsigned)g2 < (unsigned)D2 &&
                (unsigned)g3 < (unsigned)D3)
                v = ((const float4*)src)[((g1*D2 + g2)*D3 + g3)*12 + (lane - 1)];
            if (lane < 15)
                ((float4*)sIn)[r*15 + lane] = v;
        }
        __syncthreads();

        const float2* wci = sW + ci * 270;
        #pragma unroll 1
        for (int k1 = 0; k1 < 3; ++k1) {
            #pragma unroll
            for (int k23 = 0; k23 < 9; ++k23) {
                const int k2 = k23 / 3, k3 = k23 % 3;
                const float4* ip = (const float4*)
                    (sIn + (((x1l + k1)*6 + (x2l + k2))*10 + (x3l + k3))*30)
                    + q * 6;
                IV16 u;
                #pragma unroll
                for (int j = 0; j < 8; ++j) u.a[j] = ip[j];

                const float2* wp = wci + (k1*9 + k23)*10;
                float4 wA = ((const float4*)wp)[0];
                float4 wB = ((const float4*)wp)[1];
                float2 w8 = wp[8];
                float2 w[9] = {
                    make_float2(wA.x, wA.y), make_float2(wA.z, wA.w),
                    make_float2(wB.x, wB.y), make_float2(wB.z, wB.w),
                    ((const float2*)wp)[4],  ((const float2*)wp)[5],
                    ((const float2*)wp)[6],  ((const float2*)wp)[7],
                    w8 };
                #pragma unroll
                for (int co = 0; co < 3; ++co)
                    #pragma unroll
                    for (int k4 = 0; k4 < 3; ++k4) {
                        float2 wv = w[co*3 + k4];
                        #pragma unroll
                        for (int j = 0; j < 12; ++j)
                            acc[co][j] = ffma2(u.f2[j + k4 + 1], wv, acc[co][j]);
                    }
            }
        }
    }

    const int x1 = x1g + x1l, x2 = x2g + x2l, x3 = x3g + x3l;
    const int base = ((x1*D2 + x2)*D3 + x3)*D4 + q*12;
    #pragma unroll
    for (int co = 0; co < 3; ++co) {
        float4* op = (float4*)(out + co*NSP + base);
        #pragma unroll
        for (int j2 = 0; j2 < 6; ++j2)
            op[j2] = make_float4(acc[co][2*j2].x,   acc[co][2*j2].y,
                                 acc[co][2*j2+1].x, acc[co][2*j2+1].y);
    }
}

// ---------------------------------------------------------------------------
// W1 conv: 3->3 ch, (3,3,3,1) taps, pad (1,1,1,0)
// Same tiling; no x4 halo. Row stride 26 f2 = 208B = 13*16B (conflict-free).
// ---------------------------------------------------------------------------
#define W1_SMEM_F2 (3*27*4 + 4*6*10*26)    // 324 + 6240 = 6564 f2 = 52512 B

__global__ __launch_bounds__(128, 3) void w1_kernel(
    const float2* __restrict__ g,
    const float*  __restrict__ W,  const float* __restrict__ bias,
    float2* __restrict__ out)
{
    extern __shared__ float2 dsm[];
    float2* sW  = dsm;                 // [ci*27+k][4]: co in 0..2, pad 3
    float2* sIn = dsm + 3*27*4;        // [p1][p2][p3][26]

    const int tid = threadIdx.x;
    const int x3l = tid & 7;
    const int q   = (tid >> 3) & 1;
    const int x2l = (tid >> 4) & 3;
    const int x1l = tid >> 6;
    const int x1g = blockIdx.x * 2;
    const int x2g = blockIdx.y * 4;
    const int x3g = blockIdx.z * 8;

    for (int s = tid; s < 3*27; s += 128) {
        int ci = s / 27, k = s % 27;
        #pragma unroll
        for (int co = 0; co < 3; ++co) {
            float w = W[(co*3 + ci)*27 + k];
            sW[s*4 + co] = make_float2(w, w);
        }
    }

    float2 acc[3][12];
    #pragma unroll
    for (int co = 0; co < 3; ++co) {
        float b = __ldg(bias + co);
        #pragma unroll
        for (int j = 0; j < 12; ++j) acc[co][j] = make_float2(b, b);
    }

    const int lane = tid & 15;   // float4 column 0..12 (13,14,15 idle)
    const int slot = tid >> 4;

    for (int ci = 0; ci < 3; ++ci) {
        const float2* __restrict__ src = g + ci * NSP;
        __syncthreads();
        for (int r = slot; r < 240; r += 8) {
            int p3 = r % 10; int t = r / 10; int p2 = t % 6; int p1 = t / 6;
            int g1 = x1g - 1 + p1, g2 = x2g - 1 + p2, g3 = x3g - 1 + p3;
            float4 v = make_float4(0.f, 0.f, 0.f, 0.f);
            if (lane < 12 &&
                (unsigned)g1 < (unsigned)D1 && (unsigned)g2 < (unsigned)D2 &&
                (unsigned)g3 < (unsigned)D3)
                v = ((const float4*)src)[((g1*D2 + g2)*D3 + g3)*12 + lane];
            if (lane < 13)
                ((float4*)sIn)[r*13 + lane] = v;
        }
        __syncthreads();

        const float2* wci = sW + ci * 108;
        #pragma unroll 1
        for (int k1 = 0; k1 < 3; ++k1) {
            #pragma unroll
            for (int k23 = 0; k23 < 9; ++k23) {
                const int k2 = k23 / 3, k3 = k23 % 3;
                const float4* ip = (const float4*)
                    (sIn + (((x1l + k1)*6 + (x2l + k2))*10 + (x3l + k3))*26)
                    + q * 6;
                IV12 u;
                #pragma unroll
                for (int j = 0; j < 6; ++j) u.a[j] = ip[j];

                const float2* wp = wci + (k1*9 + k23)*4;
                float4 wv4 = ((const float4*)wp)[0];
                float2 w0 = make_float2(wv4.x, wv4.y);
                float2 w1 = make_float2(wv4.z, wv4.w);
                float2 w2 = wp[2];
                #pragma unroll
                for (int j = 0; j < 12; ++j) {
                    acc[0][j] = ffma2(u.f2[j], w0, acc[0][j]);
                    acc[1][j] = ffma2(u.f2[j], w1, acc[1][j]);
                    acc[2][j] = ffma2(u.f2[j], w2, acc[2][j]);
                }
            }
        }
    }

    const int x1 = x1g + x1l, x2 = x2g + x2l, x3 = x3g + x3l;
    const int base = ((x1*D2 + x2)*D3 + x3)*D4 + q*12;
    #pragma unroll
    for (int co = 0; co < 3; ++co) {
        float4* op = (float4*)(out + co*NSP + base);
        #pragma unroll
        for (int j2 = 0; j2 < 6; ++j2)
            op[j2] = make_float4(acc[co][2*j2].x,   acc[co][2*j2].y,
                                 acc[co][2*j2+1].x, acc[co][2*j2+1].y);
    }
}

// ---------------------------------------------------------------------------
// Fused epilogue: out_new = conv(t, W2, pad(0,0,0,1)) + b2 + conv(out, Wd) + bd
// ---------------------------------------------------------------------------
__global__ void w2wd_kernel(
    const float2* __restrict__ t,  const float2* __restrict__ op,
    const float*  __restrict__ W2, const float* __restrict__ b2,
    const float*  __restrict__ Wd, const float* __restrict__ bd,
    float2* __restrict__ onew, float* __restrict__ ofinal, int final_layer)
{
    int i = blockIdx.x * blockDim.x + threadIdx.x;
    if (i >= NSP) return;
    int x4 = i % D4;

    float w2r[3][3][3], wdr[3][3];
    #pragma unroll
    for (int co = 0; co < 3; ++co) {
        #pragma unroll
        for (int ci = 0; ci < 3; ++ci) {
            #pragma unroll
            for (int k = 0; k < 3; ++k)
                w2r[co][ci][k] = W2[(co*3 + ci)*3 + k];
            wdr[co][ci] = Wd[co*3 + ci];
        }
    }

    float2 acc[3];
    #pragma unroll
    for (int co = 0; co < 3; ++co) {
        float b = b2[co] + bd[co];
        acc[co] = make_float2(b, b);
    }

    const float2 z = make_float2(0.f, 0.f);
    #pragma unroll
    for (int ci = 0; ci < 3; ++ci) {
        float2 tm = (x4 > 0)      ? t[ci*NSP + i - 1] : z;
        float2 t0 =                 t[ci*NSP + i];
        float2 tp = (x4 < D4 - 1) ? t[ci*NSP + i + 1] : z;
        float2 ov =                 op[ci*NSP + i];
        #pragma unroll
        for (int co = 0; co < 3; ++co) {
            float2 a = acc[co];
            a = ffma2(make_float2(tm.x, tm.y),
                      make_float2(w2r[co][ci][0], w2r[co][ci][0]), a);
            a = ffma2(t0, make_float2(w2r[co][ci][1], w2r[co][ci][1]), a);
            a = ffma2(tp, make_float2(w2r[co][ci][2], w2r[co][ci][2]), a);
            a = ffma2(ov, make_float2(wdr[co][ci],    wdr[co][ci]),    a);
            acc[co] = a;
        }
    }

    if (final_layer) {
        #pragma unroll
        for (int co = 0; co < 3; ++co) {
            ofinal[co*NSP + i]      = acc[co].x;
            ofinal[CN + co*NSP + i] = acc[co].y;
        }
    } else {
        #pragma unroll
        for (int co = 0; co < 3; ++co)
            onew[co*NSP + i] = acc[co];
    }
}

// ---------------------------------------------------------------------------
// Driver
// ---------------------------------------------------------------------------
extern "C" void kernel_launch(void* const* d_in, const int* in_sizes, int n_in,
                              void* d_out, int out_size)
{
    const float* f   = (const float*)d_in[0];
    const float* bnd = (const float*)d_in[1];
    const float* Wg  = (const float*)d_in[2];
    const float* bg  = (const float*)d_in[3];
    const float* W1  = (const float*)d_in[4];
    const float* b1  = (const float*)d_in[5];
    const float* W2  = (const float*)d_in[6];
    const float* b2  = (const float*)d_in[7];
    const float* Wd  = (const float*)d_in[8];
    const float* bd  = (const float*)d_in[9];

    static bool attr_done = false;
    if (!attr_done) {
        cudaFuncSetAttribute(wg_kernel,
            cudaFuncAttributeMaxDynamicSharedMemorySize, WG_SMEM_F2 * 8);
        cudaFuncSetAttribute(w1_kernel,
            cudaFuncAttributeMaxDynamicSharedMemorySize, W1_SMEM_F2 * 8);
        attr_done = true;
    }

    float2 *fi, *bi, *gg, *tt, *oA, *oB;
    cudaGetSymbolAddress((void**)&fi, s_fi);
    cudaGetSymbolAddress((void**)&bi, s_bi);
    cudaGetSymbolAddress((void**)&gg, s_g);
    cudaGetSymbolAddress((void**)&tt, s_t);
    cudaGetSymbolAddress((void**)&oA, s_oA);
    cudaGetSymbolAddress((void**)&oB, s_oB);

    pack_kernel<<<(CN/4 + 255) / 256, 256>>>(
        (const float4*)f, (const float4*)bnd, (float4*)fi, (float4*)bi);

    dim3 cgrid(D1/2, D2/4, D3/8);
    const float2* cur = fi;
    float2* outs[LAYERS] = {oA, oB, oA, nullptr};

    for (int i = 0; i < LAYERS; ++i) {
        wg_kernel<<<cgrid, 128, WG_SMEM_F2 * 8>>>(
            cur, bi, Wg + i*1458, bg + i*3, gg);
        w1_kernel<<<cgrid, 128, W1_SMEM_F2 * 8>>>(
            gg, W1 + i*243, b1 + i*3, tt);
        w2wd_kernel<<<(NSP + 255) / 256, 256>>>(
            tt, cur, W2 + i*27, b2 + i*3, Wd + i*9, bd + i*3,
            outs[i], (float*)d_out, (i == LAYERS - 1) ? 1 : 0);
        cur = outs[i];
    }
}

// round 5
// speedup vs baseline: 1.0921x; 1.0053x over previous
#include <cuda_runtime.h>
#include <cuda_bf16.h>

// ---------------------------------------------------------------------------
// Problem constants
// ---------------------------------------------------------------------------
#define LAYERS 4
#define NC 3
#define D1 48
#define D2 48
#define D3 48
#define D4 24
#define NSP  (D1*D2*D3*D4)        // 2,654,208 spatial points per channel
#define CN   (NC*NSP)             // 7,962,624 elems per batch image

// ---------------------------------------------------------------------------
// Scratch: batch-interleaved tensors, float2 = {b0, b1}
// ---------------------------------------------------------------------------
__device__ float2 s_fi[CN];
__device__ float2 s_bi[CN];
__device__ float2 s_g [CN];
__device__ float2 s_t [CN];
__device__ float2 s_oA[CN];
__device__ float2 s_oB[CN];

// packed fp32x2 FMA (FFMA2) — full-rate fp32 path on sm_103a
__device__ __forceinline__ float2 ffma2(float2 a, float2 b, float2 c) {
    unsigned long long ua, ub, uc, ud;
    ua = *reinterpret_cast<const unsigned long long*>(&a);
    ub = *reinterpret_cast<const unsigned long long*>(&b);
    uc = *reinterpret_cast<const unsigned long long*>(&c);
    asm("fma.rn.f32x2 %0, %1, %2, %3;" : "=l"(ud) : "l"(ua), "l"(ub), "l"(uc));
    return *reinterpret_cast<float2*>(&ud);
}

union IV16 { float4 a[8]; float2 f2[16]; };
union IV12 { float4 a[6]; float2 f2[12]; };

__global__ void dummy_kernel() {}

// ---------------------------------------------------------------------------
// Pack f / boundary into interleaved layout (float4 path)
// ---------------------------------------------------------------------------
__global__ void pack_kernel(const float4* __restrict__ f,
                            const float4* __restrict__ bnd,
                            float4* __restrict__ fi,
                            float4* __restrict__ bi) {
    int i = blockIdx.x * blockDim.x + threadIdx.x;   // i over CN/4
    if (i >= CN / 4) return;
    float4 a = f[i],   b = f[i + CN / 4];
    fi[2*i]     = make_float4(a.x, b.x, a.y, b.y);
    fi[2*i + 1] = make_float4(a.z, b.z, a.w, b.w);
    a = bnd[i]; b = bnd[i + CN / 4];
    bi[2*i]     = make_float4(a.x, b.x, a.y, b.y);
    bi[2*i + 1] = make_float4(a.z, b.z, a.w, b.w);
}

// ---------------------------------------------------------------------------
// Wg conv: 6 in ch, 3 out ch, 3x3x3x3 taps, pad (1,1,1,1)
// Tile: x1=2, x2=4, x3=8, x4=24. 128 threads, 12 x4-outputs per thread.
// ---------------------------------------------------------------------------
#define WG_SMEM_F2 (6*27*10 + 4*6*10*30)   // 1620 + 7200 = 8820 f2 = 70560 B

__global__ __launch_bounds__(128, 3) void wg_kernel(
    const float2* __restrict__ inA, const float2* __restrict__ inB,
    const float*  __restrict__ W,   const float*  __restrict__ bias,
    float2* __restrict__ out)
{
    extern __shared__ float2 dsm[];
    float2* sW  = dsm;                 // [ci*27+k][10]: co*3+k4 in 0..8, pad 9
    float2* sIn = dsm + 6*27*10;       // [p1][p2][p3][30]

    const int tid = threadIdx.x;
    const int x3l = tid & 7;
    const int q   = (tid >> 3) & 1;    // x4 half: outputs q*12 .. q*12+11
    const int x2l = (tid >> 4) & 3;
    const int x1l = tid >> 6;          // 0..1
    const int x1g = blockIdx.x * 2;
    const int x2g = blockIdx.y * 4;
    const int x3g = blockIdx.z * 8;

    // weights -> smem, duplicated to f32x2
    for (int s = tid; s < 6*27; s += 128) {
        int ci = s / 27, k = s % 27;
        #pragma unroll
        for (int e = 0; e < 9; ++e) {
            int co = e / 3, k4 = e % 3;
            float w = W[(co*6 + ci)*81 + k*3 + k4];
            sW[s*10 + e] = make_float2(w, w);
        }
    }

    float2 acc[3][12];
    #pragma unroll
    for (int co = 0; co < 3; ++co) {
        float b = __ldg(bias + co);
        #pragma unroll
        for (int j = 0; j < 12; ++j) acc[co][j] = make_float2(b, b);
    }

    const int lane = tid & 15;   // staging: float4 column 0..14 (15 idle)
    const int slot = tid >> 4;   // staging: row slot 0..7

    for (int ci = 0; ci < 6; ++ci) {
        const float2* __restrict__ src =
            (ci < 3) ? (inA + ci * NSP) : (inB + (ci - 3) * NSP);
        __syncthreads();
        // stage [4][6][10] rows of 15 float4 (p4 = g4+2, interior g4 0..23)
        for (int r = slot; r < 240; r += 8) {
            int p3 = r % 10; int t = r / 10; int p2 = t % 6; int p1 = t / 6;
            int g1 = x1g - 1 + p1, g2 = x2g - 1 + p2, g3 = x3g - 1 + p3;
            float4 v = make_float4(0.f, 0.f, 0.f, 0.f);
            if (lane >= 1 && lane <= 12 &&
                (unsigned)g1 < (unsigned)D1 && (unsigned)g2 < (unsigned)D2 &&
                (unsigned)g3 < (unsigned)D3)
                v = ((const float4*)src)[((g1*D2 + g2)*D3 + g3)*12 + (lane - 1)];
            if (lane < 15)
                ((float4*)sIn)[r*15 + lane] = v;
        }
        __syncthreads();

        const float2* wci = sW + ci * 270;
        #pragma unroll 1
        for (int k1 = 0; k1 < 3; ++k1) {
            #pragma unroll
            for (int k23 = 0; k23 < 9; ++k23) {
                const int k2 = k23 / 3, k3 = k23 % 3;
                const float4* ip = (const float4*)
                    (sIn + (((x1l + k1)*6 + (x2l + k2))*10 + (x3l + k3))*30)
                    + q * 6;
                IV16 u;
                #pragma unroll
                for (int j = 0; j < 8; ++j) u.a[j] = ip[j];

                const float2* wp = wci + (k1*9 + k23)*10;
                float4 wA = ((const float4*)wp)[0];
                float4 wB = ((const float4*)wp)[1];
                float2 w8 = wp[8];
                float2 w[9] = {
                    make_float2(wA.x, wA.y), make_float2(wA.z, wA.w),
                    make_float2(wB.x, wB.y), make_float2(wB.z, wB.w),
                    ((const float2*)wp)[4],  ((const float2*)wp)[5],
                    ((const float2*)wp)[6],  ((const float2*)wp)[7],
                    w8 };
                #pragma unroll
                for (int co = 0; co < 3; ++co)
                    #pragma unroll
                    for (int k4 = 0; k4 < 3; ++k4) {
                        float2 wv = w[co*3 + k4];
                        #pragma unroll
                        for (int j = 0; j < 12; ++j)
                            acc[co][j] = ffma2(u.f2[j + k4 + 1], wv, acc[co][j]);
                    }
            }
        }
    }

    const int x1 = x1g + x1l, x2 = x2g + x2l, x3 = x3g + x3l;
    const int base = ((x1*D2 + x2)*D3 + x3)*D4 + q*12;
    #pragma unroll
    for (int co = 0; co < 3; ++co) {
        float4* op = (float4*)(out + co*NSP + base);
        #pragma unroll
        for (int j2 = 0; j2 < 6; ++j2)
            op[j2] = make_float4(acc[co][2*j2].x,   acc[co][2*j2].y,
                                 acc[co][2*j2+1].x, acc[co][2*j2+1].y);
    }
}

// ---------------------------------------------------------------------------
// W1 conv: 3->3 ch, (3,3,3,1) taps, pad (1,1,1,0)
// ---------------------------------------------------------------------------
#define W1_SMEM_F2 (3*27*4 + 4*6*10*26)    // 324 + 6240 = 6564 f2 = 52512 B

__global__ __launch_bounds__(128, 3) void w1_kernel(
    const float2* __restrict__ g,
    const float*  __restrict__ W,  const float* __restrict__ bias,
    float2* __restrict__ out)
{
    extern __shared__ float2 dsm[];
    float2* sW  = dsm;                 // [ci*27+k][4]: co in 0..2, pad 3
    float2* sIn = dsm + 3*27*4;        // [p1][p2][p3][26]

    const int tid = threadIdx.x;
    const int x3l = tid & 7;
    const int q   = (tid >> 3) & 1;
    const int x2l = (tid >> 4) & 3;
    const int x1l = tid >> 6;
    const int x1g = blockIdx.x * 2;
    const int x2g = blockIdx.y * 4;
    const int x3g = blockIdx.z * 8;

    for (int s = tid; s < 3*27; s += 128) {
        int ci = s / 27, k = s % 27;
        #pragma unroll
        for (int co = 0; co < 3; ++co) {
            float w = W[(co*3 + ci)*27 + k];
            sW[s*4 + co] = make_float2(w, w);
        }
    }

    float2 acc[3][12];
    #pragma unroll
    for (int co = 0; co < 3; ++co) {
        float b = __ldg(bias + co);
        #pragma unroll
        for (int j = 0; j < 12; ++j) acc[co][j] = make_float2(b, b);
    }

    const int lane = tid & 15;   // float4 column 0..12 (13,14,15 idle)
    const int slot = tid >> 4;

    for (int ci = 0; ci < 3; ++ci) {
        const float2* __restrict__ src = g + ci * NSP;
        __syncthreads();
        for (int r = slot; r < 240; r += 8) {
            int p3 = r % 10; int t = r / 10; int p2 = t % 6; int p1 = t / 6;
            int g1 = x1g - 1 + p1, g2 = x2g - 1 + p2, g3 = x3g - 1 + p3;
            float4 v = make_float4(0.f, 0.f, 0.f, 0.f);
            if (lane < 12 &&
                (unsigned)g1 < (unsigned)D1 && (unsigned)g2 < (unsigned)D2 &&
                (unsigned)g3 < (unsigned)D3)
                v = ((const float4*)src)[((g1*D2 + g2)*D3 + g3)*12 + lane];
            if (lane < 13)
                ((float4*)sIn)[r*13 + lane] = v;
        }
        __syncthreads();

        const float2* wci = sW + ci * 108;
        #pragma unroll 1
        for (int k1 = 0; k1 < 3; ++k1) {
            #pragma unroll
            for (int k23 = 0; k23 < 9; ++k23) {
                const int k2 = k23 / 3, k3 = k23 % 3;
                const float4* ip = (const float4*)
                    (sIn + (((x1l + k1)*6 + (x2l + k2))*10 + (x3l + k3))*26)
                    + q * 6;
                IV12 u;
                #pragma unroll
                for (int j = 0; j < 6; ++j) u.a[j] = ip[j];

                const float2* wp = wci + (k1*9 + k23)*4;
                float4 wv4 = ((const float4*)wp)[0];
                float2 w0 = make_float2(wv4.x, wv4.y);
                float2 w1 = make_float2(wv4.z, wv4.w);
                float2 w2 = wp[2];
                #pragma unroll
                for (int j = 0; j < 12; ++j) {
                    acc[0][j] = ffma2(u.f2[j], w0, acc[0][j]);
                    acc[1][j] = ffma2(u.f2[j], w1, acc[1][j]);
                    acc[2][j] = ffma2(u.f2[j], w2, acc[2][j]);
                }
            }
        }
    }

    const int x1 = x1g + x1l, x2 = x2g + x2l, x3 = x3g + x3l;
    const int base = ((x1*D2 + x2)*D3 + x3)*D4 + q*12;
    #pragma unroll
    for (int co = 0; co < 3; ++co) {
        float4* op = (float4*)(out + co*NSP + base);
        #pragma unroll
        for (int j2 = 0; j2 < 6; ++j2)
            op[j2] = make_float4(acc[co][2*j2].x,   acc[co][2*j2].y,
                                 acc[co][2*j2+1].x, acc[co][2*j2+1].y);
    }
}

// ---------------------------------------------------------------------------
// Fused epilogue: out_new = conv(t, W2, pad(0,0,0,1)) + b2 + conv(out, Wd) + bd
// ---------------------------------------------------------------------------
__global__ void w2wd_kernel(
    const float2* __restrict__ t,  const float2* __restrict__ op,
    const float*  __restrict__ W2, const float* __restrict__ b2,
    const float*  __restrict__ Wd, const float* __restrict__ bd,
    float2* __restrict__ onew, float* __restrict__ ofinal, int final_layer)
{
    int i = blockIdx.x * blockDim.x + threadIdx.x;
    if (i >= NSP) return;
    int x4 = i % D4;

    float w2r[3][3][3], wdr[3][3];
    #pragma unroll
    for (int co = 0; co < 3; ++co) {
        #pragma unroll
        for (int ci = 0; ci < 3; ++ci) {
            #pragma unroll
            for (int k = 0; k < 3; ++k)
                w2r[co][ci][k] = W2[(co*3 + ci)*3 + k];
            wdr[co][ci] = Wd[co*3 + ci];
        }
    }

    float2 acc[3];
    #pragma unroll
    for (int co = 0; co < 3; ++co) {
        float b = b2[co] + bd[co];
        acc[co] = make_float2(b, b);
    }

    const float2 z = make_float2(0.f, 0.f);
    #pragma unroll
    for (int ci = 0; ci < 3; ++ci) {
        float2 tm = (x4 > 0)      ? t[ci*NSP + i - 1] : z;
        float2 t0 =                 t[ci*NSP + i];
        float2 tp = (x4 < D4 - 1) ? t[ci*NSP + i + 1] : z;
        float2 ov =                 op[ci*NSP + i];
        #pragma unroll
        for (int co = 0; co < 3; ++co) {
            float2 a = acc[co];
            a = ffma2(make_float2(tm.x, tm.y),
                      make_float2(w2r[co][ci][0], w2r[co][ci][0]), a);
            a = ffma2(t0, make_float2(w2r[co][ci][1], w2r[co][ci][1]), a);
            a = ffma2(tp, make_float2(w2r[co][ci][2], w2r[co][ci][2]), a);
            a = ffma2(ov, make_float2(wdr[co][ci],    wdr[co][ci]),    a);
            acc[co] = a;
        }
    }

    if (final_layer) {
        #pragma unroll
        for (int co = 0; co < 3; ++co) {
            ofinal[co*NSP + i]      = acc[co].x;
            ofinal[CN + co*NSP + i] = acc[co].y;
        }
    } else {
        #pragma unroll
        for (int co = 0; co < 3; ++co)
            onew[co*NSP + i] = acc[co];
    }
}

// ---------------------------------------------------------------------------
// Driver
// ---------------------------------------------------------------------------
extern "C" void kernel_launch(void* const* d_in, const int* in_sizes, int n_in,
                              void* d_out, int out_size)
{
    const float* f   = (const float*)d_in[0];
    const float* bnd = (const float*)d_in[1];
    const float* Wg  = (const float*)d_in[2];
    const float* bg  = (const float*)d_in[3];
    const float* W1  = (const float*)d_in[4];
    const float* b1  = (const float*)d_in[5];
    const float* W2  = (const float*)d_in[6];
    const float* b2  = (const float*)d_in[7];
    const float* Wd  = (const float*)d_in[8];
    const float* bd  = (const float*)d_in[9];

    static bool attr_done = false;
    if (!attr_done) {
        cudaFuncSetAttribute(wg_kernel,
            cudaFuncAttributeMaxDynamicSharedMemorySize, WG_SMEM_F2 * 8);
        cudaFuncSetAttribute(w1_kernel,
            cudaFuncAttributeMaxDynamicSharedMemorySize, W1_SMEM_F2 * 8);
        attr_done = true;
    }

    float2 *fi, *bi, *gg, *tt, *oA, *oB;
    cudaGetSymbolAddress((void**)&fi, s_fi);
    cudaGetSymbolAddress((void**)&bi, s_bi);
    cudaGetSymbolAddress((void**)&gg, s_g);
    cudaGetSymbolAddress((void**)&tt, s_t);
    cudaGetSymbolAddress((void**)&oA, s_oA);
    cudaGetSymbolAddress((void**)&oB, s_oB);

    pack_kernel<<<(CN/4 + 255) / 256, 256>>>(
        (const float4*)f, (const float4*)bnd, (float4*)fi, (float4*)bi);

    // ncu alignment: with the 2 harness pre-launches observed in R1/R2,
    // these two dummies put the first wg_kernel at overall launch #6
    // (the `-s 5 -c 1` capture slot).
    dummy_kernel<<<1, 32>>>();
    dummy_kernel<<<1, 32>>>();

    dim3 cgrid(D1/2, D2/4, D3/8);
    const float2* cur = fi;
    float2* outs[LAYERS] = {oA, oB, oA, nullptr};

    for (int i = 0; i < LAYERS; ++i) {
        wg_kernel<<<cgrid, 128, WG_SMEM_F2 * 8>>>(
            cur, bi, Wg + i*1458, bg + i*3, gg);
        w1_kernel<<<cgrid, 128, W1_SMEM_F2 * 8>>>(
            gg, W1 + i*243, b1 + i*3, tt);
        w2wd_kernel<<<(NSP + 255) / 256, 256>>>(
            tt, cur, W2 + i*27, b2 + i*3, Wd + i*9, bd + i*3,
            outs[i], (float*)d_out, (i == LAYERS - 1) ? 1 : 0);
        cur = outs[i];
    }
}

// round 6
// speedup vs baseline: 1.4330x; 1.3122x over previous
#include <cuda_runtime.h>
#include <cuda_bf16.h>

// ---------------------------------------------------------------------------
// Problem constants
// ---------------------------------------------------------------------------
#define LAYERS 4
#define NC 3
#define D1 48
#define D2 48
#define D3 48
#define D4 24
#define NSP  (D1*D2*D3*D4)        // 2,654,208 spatial points per channel
#define CN   (NC*NSP)             // 7,962,624 elems per batch image

// Scratch: batch-interleaved tensors, float2 = {b0, b1}
__device__ float2 s_fi[CN];
__device__ float2 s_bi[CN];
__device__ float2 s_g [CN];
__device__ float2 s_t [CN];
__device__ float2 s_oA[CN];
__device__ float2 s_oB[CN];

// packed fp32x2 FMA (FFMA2) — full-rate fp32 path on sm_103a
__device__ __forceinline__ float2 ffma2(float2 a, float2 b, float2 c) {
    unsigned long long ua, ub, uc, ud;
    ua = *reinterpret_cast<const unsigned long long*>(&a);
    ub = *reinterpret_cast<const unsigned long long*>(&b);
    uc = *reinterpret_cast<const unsigned long long*>(&c);
    asm("fma.rn.f32x2 %0, %1, %2, %3;" : "=l"(ud) : "l"(ua), "l"(ub), "l"(uc));
    return *reinterpret_cast<float2*>(&ud);
}

__global__ void dummy_kernel() {}

// ---------------------------------------------------------------------------
// Pack f / boundary into interleaved layout
// ---------------------------------------------------------------------------
__global__ void pack_kernel(const float4* __restrict__ f,
                            const float4* __restrict__ bnd,
                            float4* __restrict__ fi,
                            float4* __restrict__ bi) {
    int i = blockIdx.x * blockDim.x + threadIdx.x;
    if (i >= CN / 4) return;
    float4 a = f[i],   b = f[i + CN / 4];
    fi[2*i]     = make_float4(a.x, b.x, a.y, b.y);
    fi[2*i + 1] = make_float4(a.z, b.z, a.w, b.w);
    a = bnd[i]; b = bnd[i + CN / 4];
    bi[2*i]     = make_float4(a.x, b.x, a.y, b.y);
    bi[2*i + 1] = make_float4(a.z, b.z, a.w, b.w);
}

// ---------------------------------------------------------------------------
// Wg conv: 6 in ch, 3 out ch, 3x3x3x3 taps, pad (1,1,1,1)
// Tile: x1=2, x2=4, x3=8, x4=24.  256 threads, 6 x4-outputs per thread.
// smem: input stage [4][6][10] rows x 30 f2 (stride 15 f4, odd -> LDS.128
// quarter-warp phases are pure-x3l and conflict-free) + scalar weights
// [6*27][12] (pairs built in regs on the alu pipe).
// ---------------------------------------------------------------------------
#define WG_STAGE_F2 (240*30)                       // 7200 f2 = 57600 B
#define WG_SMEM     (WG_STAGE_F2*8 + 162*12*4)     // 57600 + 7776 = 65376 B

__global__ __launch_bounds__(256, 2) void wg_kernel(
    const float2* __restrict__ inA, const float2* __restrict__ inB,
    const float*  __restrict__ W,   const float*  __restrict__ bias,
    float2* __restrict__ out)
{
    extern __shared__ float2 dsm[];
    float2* sIn = dsm;                         // [row][30]
    float*  sW  = (float*)(dsm + WG_STAGE_F2); // [ci*27+k][12]: e=co*3+k4 in 0..8

    const int tid = threadIdx.x;
    const int x3l = tid & 7;
    const int q   = (tid >> 3) & 3;    // x4 quarter: outputs q*6 .. q*6+5
    const int x2l = (tid >> 5) & 3;
    const int x1l = tid >> 7;          // 0..1
    const int x1g = blockIdx.x * 2;
    const int x2g = blockIdx.y * 4;
    const int x3g = blockIdx.z * 8;

    // scalar weights -> smem (padded groups of 12 for 16B-aligned loads)
    for (int s = tid; s < 162*9; s += 256) {
        int grp = s / 9, e = s % 9;
        int ci = grp / 27, k = grp % 27;
        int co = e / 3, k4 = e % 3;
        sW[grp*12 + e] = W[(co*6 + ci)*81 + k*3 + k4];
    }

    float2 acc[3][6];
    #pragma unroll
    for (int co = 0; co < 3; ++co) {
        float b = __ldg(bias + co);
        #pragma unroll
        for (int j = 0; j < 6; ++j) acc[co][j] = make_float2(b, b);
    }

    for (int ci = 0; ci < 6; ++ci) {
        const float2* __restrict__ src =
            (ci < 3) ? (inA + ci * NSP) : (inB + (ci - 3) * NSP);
        __syncthreads();
        // stage 240 rows x 15 float4; f2 col c <-> g4 = c-2 (cols 2..25 data)
        for (int idx = tid; idx < 240*15; idx += 256) {
            int row = idx / 15, c = idx % 15;
            int p3 = row % 10; int t = row / 10; int p2 = t % 6; int p1 = t / 6;
            int g1 = x1g - 1 + p1, g2 = x2g - 1 + p2, g3 = x3g - 1 + p3;
            float4 v = make_float4(0.f, 0.f, 0.f, 0.f);
            if (c >= 1 && c <= 12 &&
                (unsigned)g1 < (unsigned)D1 && (unsigned)g2 < (unsigned)D2 &&
                (unsigned)g3 < (unsigned)D3)
                v = ((const float4*)src)[((g1*D2 + g2)*D3 + g3)*12 + (c - 1)];
            ((float4*)sIn)[row*15 + c] = v;
        }
        __syncthreads();

        const float* wci = sW + ci * 27 * 12;
        #pragma unroll 1
        for (int k1 = 0; k1 < 3; ++k1) {
            #pragma unroll
            for (int k23 = 0; k23 < 9; ++k23) {
                const int k2 = k23 / 3, k3 = k23 % 3;
                const float4* ip = (const float4*)sIn
                    + (((x1l + k1)*6 + (x2l + k2))*10 + (x3l + k3))*15 + q*3;
                float4 a4[5];
                #pragma unroll
                for (int m = 0; m < 5; ++m) a4[m] = ip[m];
                const float2* uf = reinterpret_cast<const float2*>(a4);

                const float* wp = wci + (k1*9 + k23)*12;
                float4 wa = ((const float4*)wp)[0];
                float4 wb = ((const float4*)wp)[1];
                float w8 = wp[8];
                float ws[9] = {wa.x, wa.y, wa.z, wa.w,
                               wb.x, wb.y, wb.z, wb.w, w8};
                #pragma unroll
                for (int co = 0; co < 3; ++co)
                    #pragma unroll
                    for (int k4 = 0; k4 < 3; ++k4) {
                        float2 wv = make_float2(ws[co*3 + k4], ws[co*3 + k4]);
                        #pragma unroll
                        for (int j = 0; j < 6; ++j)
                            acc[co][j] = ffma2(uf[j + k4 + 1], wv, acc[co][j]);
                    }
            }
        }
    }

    const int x1 = x1g + x1l, x2 = x2g + x2l, x3 = x3g + x3l;
    const int base = ((x1*D2 + x2)*D3 + x3)*D4 + q*6;
    #pragma unroll
    for (int co = 0; co < 3; ++co) {
        float4* op = (float4*)(out + co*NSP + base);
        #pragma unroll
        for (int j2 = 0; j2 < 3; ++j2)
            op[j2] = make_float4(acc[co][2*j2].x,   acc[co][2*j2].y,
                                 acc[co][2*j2+1].x, acc[co][2*j2+1].y);
    }
}

// ---------------------------------------------------------------------------
// W1 conv: 3->3 ch, (3,3,3,1) taps, pad (1,1,1,0)
// 256 threads, 6 outputs/thread; stage stride 13 f4 (odd, conflict-free).
// ---------------------------------------------------------------------------
#define W1_STAGE_F2 (240*26)                       // 6240 f2 = 49920 B
#define W1_SMEM     (W1_STAGE_F2*8 + 81*4*4)       // 49920 + 1296 = 51216 B

__global__ __launch_bounds__(256, 3) void w1_kernel(
    const float2* __restrict__ g,
    const float*  __restrict__ W,  const float* __restrict__ bias,
    float2* __restrict__ out)
{
    extern __shared__ float2 dsm[];
    float2* sIn = dsm;                         // [row][26], col c <-> g4 c
    float*  sW  = (float*)(dsm + W1_STAGE_F2); // [ci*27+k][4]: co in 0..2

    const int tid = threadIdx.x;
    const int x3l = tid & 7;
    const int q   = (tid >> 3) & 3;
    const int x2l = (tid >> 5) & 3;
    const int x1l = tid >> 7;
    const int x1g = blockIdx.x * 2;
    const int x2g = blockIdx.y * 4;
    const int x3g = blockIdx.z * 8;

    for (int s = tid; s < 81*3; s += 256) {
        int grp = s / 3, co = s % 3;
        int ci = grp / 27, k = grp % 27;
        sW[grp*4 + co] = W[(co*3 + ci)*27 + k];
    }

    float2 acc[3][6];
    #pragma unroll
    for (int co = 0; co < 3; ++co) {
        float b = __ldg(bias + co);
        #pragma unroll
        for (int j = 0; j < 6; ++j) acc[co][j] = make_float2(b, b);
    }

    for (int ci = 0; ci < 3; ++ci) {
        const float2* __restrict__ src = g + ci * NSP;
        __syncthreads();
        // stage 240 rows x 12 data float4 into stride-13 rows (col 12 unused)
        for (int idx = tid; idx < 240*12; idx += 256) {
            int row = idx / 12, c = idx % 12;
            int p3 = row % 10; int t = row / 10; int p2 = t % 6; int p1 = t / 6;
            int g1 = x1g - 1 + p1, g2 = x2g - 1 + p2, g3 = x3g - 1 + p3;
            float4 v = make_float4(0.f, 0.f, 0.f, 0.f);
            if ((unsigned)g1 < (unsigned)D1 && (unsigned)g2 < (unsigned)D2 &&
                (unsigned)g3 < (unsigned)D3)
                v = ((const float4*)src)[((g1*D2 + g2)*D3 + g3)*12 + c];
            ((float4*)sIn)[row*13 + c] = v;
        }
        __syncthreads();

        const float* wci = sW + ci * 27 * 4;
        #pragma unroll 1
        for (int k1 = 0; k1 < 3; ++k1) {
            #pragma unroll
            for (int k23 = 0; k23 < 9; ++k23) {
                const int k2 = k23 / 3, k3 = k23 % 3;
                const float4* ip = (const float4*)sIn
                    + (((x1l + k1)*6 + (x2l + k2))*10 + (x3l + k3))*13 + q*3;
                float4 a4[3];
                #pragma unroll
                for (int m = 0; m < 3; ++m) a4[m] = ip[m];
                const float2* uf = reinterpret_cast<const float2*>(a4);

                float4 wv4 = *(const float4*)(wci + (k1*9 + k23)*4);
                float2 w0 = make_float2(wv4.x, wv4.x);
                float2 w1 = make_float2(wv4.y, wv4.y);
                float2 w2 = make_float2(wv4.z, wv4.z);
                #pragma unroll
                for (int j = 0; j < 6; ++j) {
                    acc[0][j] = ffma2(uf[j], w0, acc[0][j]);
                    acc[1][j] = ffma2(uf[j], w1, acc[1][j]);
                    acc[2][j] = ffma2(uf[j], w2, acc[2][j]);
                }
            }
        }
    }

    const int x1 = x1g + x1l, x2 = x2g + x2l, x3 = x3g + x3l;
    const int base = ((x1*D2 + x2)*D3 + x3)*D4 + q*6;
    #pragma unroll
    for (int co = 0; co < 3; ++co) {
        float4* op = (float4*)(out + co*NSP + base);
        #pragma unroll
        for (int j2 = 0; j2 < 3; ++j2)
            op[j2] = make_float4(acc[co][2*j2].x,   acc[co][2*j2].y,
                                 acc[co][2*j2+1].x, acc[co][2*j2+1].y);
    }
}

// ---------------------------------------------------------------------------
// Fused epilogue: out_new = conv(t, W2, pad(0,0,0,1)) + b2 + conv(out, Wd) + bd
// [UNCHANGED — passing since R1]
// ---------------------------------------------------------------------------
__global__ void w2wd_kernel(
    const float2* __restrict__ t,  const float2* __restrict__ op,
    const float*  __restrict__ W2, const float* __restrict__ b2,
    const float*  __restrict__ Wd, const float* __restrict__ bd,
    float2* __restrict__ onew, float* __restrict__ ofinal, int final_layer)
{
    int i = blockIdx.x * blockDim.x + threadIdx.x;
    if (i >= NSP) return;
    int x4 = i % D4;

    float w2r[3][3][3], wdr[3][3];
    #pragma unroll
    for (int co = 0; co < 3; ++co) {
        #pragma unroll
        for (int ci = 0; ci < 3; ++ci) {
            #pragma unroll
            for (int k = 0; k < 3; ++k)
                w2r[co][ci][k] = W2[(co*3 + ci)*3 + k];
            wdr[co][ci] = Wd[co*3 + ci];
        }
    }

    float2 acc[3];
    #pragma unroll
    for (int co = 0; co < 3; ++co) {
        float b = b2[co] + bd[co];
        acc[co] = make_float2(b, b);
    }

    const float2 z = make_float2(0.f, 0.f);
    #pragma unroll
    for (int ci = 0; ci < 3; ++ci) {
        float2 tm = (x4 > 0)      ? t[ci*NSP + i - 1] : z;
        float2 t0 =                 t[ci*NSP + i];
        float2 tp = (x4 < D4 - 1) ? t[ci*NSP + i + 1] : z;
        float2 ov =                 op[ci*NSP + i];
        #pragma unroll
        for (int co = 0; co < 3; ++co) {
            float2 a = acc[co];
            a = ffma2(tm, make_float2(w2r[co][ci][0], w2r[co][ci][0]), a);
            a = ffma2(t0, make_float2(w2r[co][ci][1], w2r[co][ci][1]), a);
            a = ffma2(tp, make_float2(w2r[co][ci][2], w2r[co][ci][2]), a);
            a = ffma2(ov, make_float2(wdr[co][ci],    wdr[co][ci]),    a);
            acc[co] = a;
        }
    }

    if (final_layer) {
        #pragma unroll
        for (int co = 0; co < 3; ++co) {
            ofinal[co*NSP + i]      = acc[co].x;
            ofinal[CN + co*NSP + i] = acc[co].y;
        }
    } else {
        #pragma unroll
        for (int co = 0; co < 3; ++co)
            onew[co*NSP + i] = acc[co];
    }
}

// ---------------------------------------------------------------------------
// Driver
// ---------------------------------------------------------------------------
extern "C" void kernel_launch(void* const* d_in, const int* in_sizes, int n_in,
                              void* d_out, int out_size)
{
    const float* f   = (const float*)d_in[0];
    const float* bnd = (const float*)d_in[1];
    const float* Wg  = (const float*)d_in[2];
    const float* bg  = (const float*)d_in[3];
    const float* W1  = (const float*)d_in[4];
    const float* b1  = (const float*)d_in[5];
    const float* W2  = (const float*)d_in[6];
    const float* b2  = (const float*)d_in[7];
    const float* Wd  = (const float*)d_in[8];
    const float* bd  = (const float*)d_in[9];

    static bool attr_done = false;
    if (!attr_done) {
        cudaFuncSetAttribute(wg_kernel,
            cudaFuncAttributeMaxDynamicSharedMemorySize, WG_SMEM);
        cudaFuncSetAttribute(w1_kernel,
            cudaFuncAttributeMaxDynamicSharedMemorySize, W1_SMEM);
        attr_done = true;
    }

    float2 *fi, *bi, *gg, *tt, *oA, *oB;
    cudaGetSymbolAddress((void**)&fi, s_fi);
    cudaGetSymbolAddress((void**)&bi, s_bi);
    cudaGetSymbolAddress((void**)&gg, s_g);
    cudaGetSymbolAddress((void**)&tt, s_t);
    cudaGetSymbolAddress((void**)&oA, s_oA);
    cudaGetSymbolAddress((void**)&oB, s_oB);

    pack_kernel<<<(CN/4 + 255) / 256, 256>>>(
        (const float4*)f, (const float4*)bnd, (float4*)fi, (float4*)bi);

    // ncu alignment (confirmed in R5): 2 harness pre-launches + pack + 2
    // dummies puts the first wg_kernel in the `-s 5 -c 1` capture slot.
    dummy_kernel<<<1, 32>>>();
    dummy_kernel<<<1, 32>>>();

    dim3 cgrid(D1/2, D2/4, D3/8);
    const float2* cur = fi;
    float2* outs[LAYERS] = {oA, oB, oA, nullptr};

    for (int i = 0; i < LAYERS; ++i) {
        wg_kernel<<<cgrid, 256, WG_SMEM>>>(
            cur, bi, Wg + i*1458, bg + i*3, gg);
        w1_kernel<<<cgrid, 256, W1_SMEM>>>(
            gg, W1 + i*243, b1 + i*3, tt);
        w2wd_kernel<<<(NSP + 255) / 256, 256>>>(
            tt, cur, W2 + i*27, b2 + i*3, Wd + i*9, bd + i*3,
            outs[i], (float*)d_out, (i == LAYERS - 1) ? 1 : 0);
        cur = outs[i];
    }
}

// round 7
// speedup vs baseline: 1.4430x; 1.0070x over previous
#include <cuda_runtime.h>
#include <cuda_bf16.h>

// ---------------------------------------------------------------------------
// Problem constants
// ---------------------------------------------------------------------------
#define LAYERS 4
#define NC 3
#define D1 48
#define D2 48
#define D3 48
#define D4 24
#define NSP  (D1*D2*D3*D4)        // 2,654,208 spatial points per channel
#define CN   (NC*NSP)             // 7,962,624 elems per batch image

// Scratch: batch-interleaved tensors, float2 = {b0, b1}
__device__ float2 s_fi[CN];
__device__ float2 s_bi[CN];
__device__ float2 s_g [CN];
__device__ float2 s_t [CN];
__device__ float2 s_oA[CN];
__device__ float2 s_oB[CN];

// packed fp32x2 FMA (FFMA2) — full-rate fp32 path on sm_103a
__device__ __forceinline__ float2 ffma2(float2 a, float2 b, float2 c) {
    unsigned long long ua, ub, uc, ud;
    ua = *reinterpret_cast<const unsigned long long*>(&a);
    ub = *reinterpret_cast<const unsigned long long*>(&b);
    uc = *reinterpret_cast<const unsigned long long*>(&c);
    asm("fma.rn.f32x2 %0, %1, %2, %3;" : "=l"(ud) : "l"(ua), "l"(ub), "l"(uc));
    return *reinterpret_cast<float2*>(&ud);
}

__global__ void dummy_kernel() {}

// ---------------------------------------------------------------------------
// Pack f / boundary into interleaved layout
// ---------------------------------------------------------------------------
__global__ void pack_kernel(const float4* __restrict__ f,
                            const float4* __restrict__ bnd,
                            float4* __restrict__ fi,
                            float4* __restrict__ bi) {
    int i = blockIdx.x * blockDim.x + threadIdx.x;
    if (i >= CN / 4) return;
    float4 a = f[i],   b = f[i + CN / 4];
    fi[2*i]     = make_float4(a.x, b.x, a.y, b.y);
    fi[2*i + 1] = make_float4(a.z, b.z, a.w, b.w);
    a = bnd[i]; b = bnd[i + CN / 4];
    bi[2*i]     = make_float4(a.x, b.x, a.y, b.y);
    bi[2*i + 1] = make_float4(a.z, b.z, a.w, b.w);
}

// ---------------------------------------------------------------------------
// Wg conv: 6 in ch, 3 out ch, 3x3x3x3 taps, pad (1,1,1,1)
// Tile: x1=2, x2=4, x3=8, x4=24.  256 threads, 6 x4-outputs per thread.
// Register-dieted for 3 blocks/SM (24 warps): dup'd f2 weights in smem
// (read per-co as LDS.64, short live ranges), u loads 4xLDS.128 + 1xLDS.64.
// smem 70560 B x 3 = 207 KB/SM.
// ---------------------------------------------------------------------------
#define WG_W_F2     (162*10)                       // 1620 f2 = 12960 B
#define WG_STAGE_F2 (240*30)                       // 7200 f2 = 57600 B
#define WG_SMEM     ((WG_W_F2 + WG_STAGE_F2)*8)    // 70560 B

__global__ __launch_bounds__(256, 3) void wg_kernel(
    const float2* __restrict__ inA, const float2* __restrict__ inB,
    const float*  __restrict__ W,   const float*  __restrict__ bias,
    float2* __restrict__ out)
{
    extern __shared__ float2 dsm[];
    float2* sW  = dsm;                 // [ci*27+k][10]: e=co*3+k4 in 0..8
    float2* sIn = dsm + WG_W_F2;       // [240 rows][15 f4], f2 col c <-> g4 c-2

    const int tid = threadIdx.x;
    const int x3l = tid & 7;
    const int q   = (tid >> 3) & 3;    // x4 quarter: outputs q*6 .. q*6+5
    const int x2l = (tid >> 5) & 3;
    const int x1l = tid >> 7;          // 0..1
    const int x1g = blockIdx.x * 2;
    const int x2g = blockIdx.y * 4;
    const int x3g = blockIdx.z * 8;

    // weights -> smem, duplicated to f2 pairs
    for (int s = tid; s < 162*9; s += 256) {
        int grp = s / 9, e = s % 9;
        int ci = grp / 27, k = grp % 27;
        int co = e / 3, k4 = e % 3;
        float w = W[(co*6 + ci)*81 + k*3 + k4];
        sW[grp*10 + e] = make_float2(w, w);
    }

    float2 acc[3][6];
    #pragma unroll
    for (int co = 0; co < 3; ++co) {
        float b = __ldg(bias + co);
        #pragma unroll
        for (int j = 0; j < 6; ++j) acc[co][j] = make_float2(b, b);
    }

    for (int ci = 0; ci < 6; ++ci) {
        const float2* __restrict__ src =
            (ci < 3) ? (inA + ci * NSP) : (inB + (ci - 3) * NSP);
        __syncthreads();
        for (int idx = tid; idx < 240*15; idx += 256) {
            int row = idx / 15, c = idx % 15;
            int p3 = row % 10; int t = row / 10; int p2 = t % 6; int p1 = t / 6;
            int g1 = x1g - 1 + p1, g2 = x2g - 1 + p2, g3 = x3g - 1 + p3;
            float4 v = make_float4(0.f, 0.f, 0.f, 0.f);
            if (c >= 1 && c <= 12 &&
                (unsigned)g1 < (unsigned)D1 && (unsigned)g2 < (unsigned)D2 &&
                (unsigned)g3 < (unsigned)D3)
                v = ((const float4*)src)[((g1*D2 + g2)*D3 + g3)*12 + (c - 1)];
            ((float4*)sIn)[row*15 + c] = v;
        }
        __syncthreads();

        const float2* wci = sW + ci * 270;
        #pragma unroll 1
        for (int k1 = 0; k1 < 3; ++k1) {
            #pragma unroll
            for (int k23 = 0; k23 < 9; ++k23) {
                const int k2 = k23 / 3, k3 = k23 % 3;
                const float4* ip = (const float4*)sIn
                    + (((x1l + k1)*6 + (x2l + k2))*10 + (x3l + k3))*15 + q*3;
                // need f2 cols 1..8 of this 9-wide window
                float4 a4[4];
                #pragma unroll
                for (int m = 0; m < 4; ++m) a4[m] = ip[m];
                float2 u8 = ((const float2*)ip)[8];
                const float2* uf = reinterpret_cast<const float2*>(a4);

                const float2* wp = wci + (k1*9 + k23)*10;
                #pragma unroll
                for (int co = 0; co < 3; ++co) {
                    float2 w0 = wp[co*3 + 0];
                    float2 w1 = wp[co*3 + 1];
                    float2 w2 = wp[co*3 + 2];
                    #pragma unroll
                    for (int j = 0; j < 6; ++j) {
                        float2 a = acc[co][j];
                        a = ffma2(uf[j + 1], w0, a);
                        a = ffma2(uf[j + 2], w1, a);
                        a = ffma2((j == 5) ? u8 : uf[j + 3], w2, a);
                        acc[co][j] = a;
                    }
                }
            }
        }
    }

    const int x1 = x1g + x1l, x2 = x2g + x2l, x3 = x3g + x3l;
    const int base = ((x1*D2 + x2)*D3 + x3)*D4 + q*6;
    #pragma unroll
    for (int co = 0; co < 3; ++co) {
        float4* op = (float4*)(out + co*NSP + base);
        #pragma unroll
        for (int j2 = 0; j2 < 3; ++j2)
            op[j2] = make_float4(acc[co][2*j2].x,   acc[co][2*j2].y,
                                 acc[co][2*j2+1].x, acc[co][2*j2+1].y);
    }
}

// ---------------------------------------------------------------------------
// W1 conv: 3->3 ch, (3,3,3,1) taps, pad (1,1,1,0)
// 256 threads, 6 outputs/thread; dup'd f2 weights, stride-13-f4 stage.
// ---------------------------------------------------------------------------
#define W1_W_F2     (81*4)                         // 324 f2 = 2592 B
#define W1_STAGE_F2 (240*26)                       // 6240 f2 = 49920 B
#define W1_SMEM     ((W1_W_F2 + W1_STAGE_F2)*8)    // 52512 B

__global__ __launch_bounds__(256, 3) void w1_kernel(
    const float2* __restrict__ g,
    const float*  __restrict__ W,  const float* __restrict__ bias,
    float2* __restrict__ out)
{
    extern __shared__ float2 dsm[];
    float2* sW  = dsm;                 // [ci*27+k][4]: co in 0..2, pad 3
    float2* sIn = dsm + W1_W_F2;       // [240 rows][13 f4], f2 col c <-> g4 c

    const int tid = threadIdx.x;
    const int x3l = tid & 7;
    const int q   = (tid >> 3) & 3;
    const int x2l = (tid >> 5) & 3;
    const int x1l = tid >> 7;
    const int x1g = blockIdx.x * 2;
    const int x2g = blockIdx.y * 4;
    const int x3g = blockIdx.z * 8;

    for (int s = tid; s < 81*3; s += 256) {
        int grp = s / 3, co = s % 3;
        int ci = grp / 27, k = grp % 27;
        float w = W[(co*3 + ci)*27 + k];
        sW[grp*4 + co] = make_float2(w, w);
    }

    float2 acc[3][6];
    #pragma unroll
    for (int co = 0; co < 3; ++co) {
        float b = __ldg(bias + co);
        #pragma unroll
        for (int j = 0; j < 6; ++j) acc[co][j] = make_float2(b, b);
    }

    for (int ci = 0; ci < 3; ++ci) {
        const float2* __restrict__ src = g + ci * NSP;
        __syncthreads();
        for (int idx = tid; idx < 240*12; idx += 256) {
            int row = idx / 12, c = idx % 12;
            int p3 = row % 10; int t = row / 10; int p2 = t % 6; int p1 = t / 6;
            int g1 = x1g - 1 + p1, g2 = x2g - 1 + p2, g3 = x3g - 1 + p3;
            float4 v = make_float4(0.f, 0.f, 0.f, 0.f);
            if ((unsigned)g1 < (unsigned)D1 && (unsigned)g2 < (unsigned)D2 &&
                (unsigned)g3 < (unsigned)D3)
                v = ((const float4*)src)[((g1*D2 + g2)*D3 + g3)*12 + c];
            ((float4*)sIn)[row*13 + c] = v;
        }
        __syncthreads();

        const float2* wci = sW + ci * 108;
        #pragma unroll 1
        for (int k1 = 0; k1 < 3; ++k1) {
            #pragma unroll
            for (int k23 = 0; k23 < 9; ++k23) {
                const int k2 = k23 / 3, k3 = k23 % 3;
                const float4* ip = (const float4*)sIn
                    + (((x1l + k1)*6 + (x2l + k2))*10 + (x3l + k3))*13 + q*3;
                float4 a4[3];
                #pragma unroll
                for (int m = 0; m < 3; ++m) a4[m] = ip[m];
                const float2* uf = reinterpret_cast<const float2*>(a4);

                const float2* wp = wci + (k1*9 + k23)*4;
                float2 w0 = wp[0];
                float2 w1 = wp[1];
                float2 w2 = wp[2];
                #pragma unroll
                for (int j = 0; j < 6; ++j) {
                    acc[0][j] = ffma2(uf[j], w0, acc[0][j]);
                    acc[1][j] = ffma2(uf[j], w1, acc[1][j]);
                    acc[2][j] = ffma2(uf[j], w2, acc[2][j]);
                }
            }
        }
    }

    const int x1 = x1g + x1l, x2 = x2g + x2l, x3 = x3g + x3l;
    const int base = ((x1*D2 + x2)*D3 + x3)*D4 + q*6;
    #pragma unroll
    for (int co = 0; co < 3; ++co) {
        float4* op = (float4*)(out + co*NSP + base);
        #pragma unroll
        for (int j2 = 0; j2 < 3; ++j2)
            op[j2] = make_float4(acc[co][2*j2].x,   acc[co][2*j2].y,
                                 acc[co][2*j2+1].x, acc[co][2*j2+1].y);
    }
}

// ---------------------------------------------------------------------------
// Fused epilogue: out_new = conv(t, W2, pad(0,0,0,1)) + b2 + conv(out, Wd) + bd
// [UNCHANGED — passing since R1]
// ---------------------------------------------------------------------------
__global__ void w2wd_kernel(
    const float2* __restrict__ t,  const float2* __restrict__ op,
    const float*  __restrict__ W2, const float* __restrict__ b2,
    const float*  __restrict__ Wd, const float* __restrict__ bd,
    float2* __restrict__ onew, float* __restrict__ ofinal, int final_layer)
{
    int i = blockIdx.x * blockDim.x + threadIdx.x;
    if (i >= NSP) return;
    int x4 = i % D4;

    float w2r[3][3][3], wdr[3][3];
    #pragma unroll
    for (int co = 0; co < 3; ++co) {
        #pragma unroll
        for (int ci = 0; ci < 3; ++ci) {
            #pragma unroll
            for (int k = 0; k < 3; ++k)
                w2r[co][ci][k] = W2[(co*3 + ci)*3 + k];
            wdr[co][ci] = Wd[co*3 + ci];
        }
    }

    float2 acc[3];
    #pragma unroll
    for (int co = 0; co < 3; ++co) {
        float b = b2[co] + bd[co];
        acc[co] = make_float2(b, b);
    }

    const float2 z = make_float2(0.f, 0.f);
    #pragma unroll
    for (int ci = 0; ci < 3; ++ci) {
        float2 tm = (x4 > 0)      ? t[ci*NSP + i - 1] : z;
        float2 t0 =                 t[ci*NSP + i];
        float2 tp = (x4 < D4 - 1) ? t[ci*NSP + i + 1] : z;
        float2 ov =                 op[ci*NSP + i];
        #pragma unroll
        for (int co = 0; co < 3; ++co) {
            float2 a = acc[co];
            a = ffma2(tm, make_float2(w2r[co][ci][0], w2r[co][ci][0]), a);
            a = ffma2(t0, make_float2(w2r[co][ci][1], w2r[co][ci][1]), a);
            a = ffma2(tp, make_float2(w2r[co][ci][2], w2r[co][ci][2]), a);
            a = ffma2(ov, make_float2(wdr[co][ci],    wdr[co][ci]),    a);
            acc[co] = a;
        }
    }

    if (final_layer) {
        #pragma unroll
        for (int co = 0; co < 3; ++co) {
            ofinal[co*NSP + i]      = acc[co].x;
            ofinal[CN + co*NSP + i] = acc[co].y;
        }
    } else {
        #pragma unroll
        for (int co = 0; co < 3; ++co)
            onew[co*NSP + i] = acc[co];
    }
}

// ---------------------------------------------------------------------------
// Driver
// ---------------------------------------------------------------------------
extern "C" void kernel_launch(void* const* d_in, const int* in_sizes, int n_in,
                              void* d_out, int out_size)
{
    const float* f   = (const float*)d_in[0];
    const float* bnd = (const float*)d_in[1];
    const float* Wg  = (const float*)d_in[2];
    const float* bg  = (const float*)d_in[3];
    const float* W1  = (const float*)d_in[4];
    const float* b1  = (const float*)d_in[5];
    const float* W2  = (const float*)d_in[6];
    const float* b2  = (const float*)d_in[7];
    const float* Wd  = (const float*)d_in[8];
    const float* bd  = (const float*)d_in[9];

    static bool attr_done = false;
    if (!attr_done) {
        cudaFuncSetAttribute(wg_kernel,
            cudaFuncAttributeMaxDynamicSharedMemorySize, WG_SMEM);
        cudaFuncSetAttribute(w1_kernel,
            cudaFuncAttributeMaxDynamicSharedMemorySize, W1_SMEM);
        attr_done = true;
    }

    float2 *fi, *bi, *gg, *tt, *oA, *oB;
    cudaGetSymbolAddress((void**)&fi, s_fi);
    cudaGetSymbolAddress((void**)&bi, s_bi);
    cudaGetSymbolAddress((void**)&gg, s_g);
    cudaGetSymbolAddress((void**)&tt, s_t);
    cudaGetSymbolAddress((void**)&oA, s_oA);
    cudaGetSymbolAddress((void**)&oB, s_oB);

    pack_kernel<<<(CN/4 + 255) / 256, 256>>>(
        (const float4*)f, (const float4*)bnd, (float4*)fi, (float4*)bi);

    // ncu alignment (confirmed R5/R6): first wg_kernel lands in the
    // `-s 5 -c 1` capture slot.
    dummy_kernel<<<1, 32>>>();
    dummy_kernel<<<1, 32>>>();

    dim3 cgrid(D1/2, D2/4, D3/8);
    const float2* cur = fi;
    float2* outs[LAYERS] = {oA, oB, oA, nullptr};

    for (int i = 0; i < LAYERS; ++i) {
        wg_kernel<<<cgrid, 256, WG_SMEM>>>(
            cur, bi, Wg + i*1458, bg + i*3, gg);
        w1_kernel<<<cgrid, 256, W1_SMEM>>>(
            gg, W1 + i*243, b1 + i*3, tt);
        w2wd_kernel<<<(NSP + 255) / 256, 256>>>(
            tt, cur, W2 + i*27, b2 + i*3, Wd + i*9, bd + i*3,
            outs[i], (float*)d_out, (i == LAYERS - 1) ? 1 : 0);
        cur = outs[i];
    }
}